// round 1
// baseline (speedup 1.0000x reference)
#include <cuda_runtime.h>
#include <cuda_bf16.h>

#define BS 128
#define NN 32
#define IN_DIM 16
#define HID 128
#define HEADS 4
#define OUTD 5
#define DUEL_H 256
#define D1 (HEADS*HID)       // 512
#define LATENT (HID + 2*D1)  // 1152
#define OBS_W (NN*(2+IN_DIM)+1) // 577
#define RAD2 0.09f

// -------- scratch (device globals; no runtime alloc allowed) --------
__device__ float g_X0 [BS*NN*HID];   // encoder out
__device__ unsigned g_ADJ[BS*NN];    // adjacency bitmask per row
__device__ float g_GL1[BS*NN*D1];
__device__ float g_GR1[BS*NN*D1];
__device__ float g_X1 [BS*NN*D1];    // relu(gat1)
__device__ float g_GL2[BS*NN*D1];
__device__ float g_GR2[BS*NN*D1];
__device__ float g_X2 [BS*NN*D1];    // relu(gat2)

// -------- encoder + adjacency: one block per batch, 128 threads --------
__global__ void enc_kernel(const float* __restrict__ obs,
                           const float* __restrict__ w1, const float* __restrict__ b1,
                           const float* __restrict__ w2, const float* __restrict__ b2,
                           float* __restrict__ X0, unsigned* __restrict__ ADJ)
{
    __shared__ float s_obs[OBS_W];
    __shared__ float s_h[NN*HID];
    int b = blockIdx.x, t = threadIdx.x;

    for (int i = t; i < OBS_W; i += 128) s_obs[i] = obs[b*OBS_W + i];
    __syncthreads();

    // adjacency bitmask (threads 0..31)
    if (t < NN) {
        float xi = s_obs[t*18 + 0], yi = s_obs[t*18 + 1];
        unsigned m = 0;
        #pragma unroll
        for (int j = 0; j < NN; j++) {
            float dx = xi - s_obs[j*18 + 0];
            float dy = yi - s_obs[j*18 + 1];
            float d2 = dx*dx + dy*dy;
            if (d2 < RAD2 || j == t) m |= (1u << j);
        }
        ADJ[b*NN + t] = m;
    }

    // h = relu(feats @ w1 + b1); thread t = output column
    float bb = b1[t];
    for (int r = 0; r < NN; r++) {
        float acc = bb;
        #pragma unroll
        for (int f = 0; f < IN_DIM; f++)
            acc += s_obs[r*18 + 2 + f] * w1[f*HID + t];
        s_h[r*HID + t] = fmaxf(acc, 0.f);
    }
    __syncthreads();

    // x = relu(h @ w2 + b2)
    float b2v = b2[t];
    for (int r = 0; r < NN; r++) {
        float acc = b2v;
        #pragma unroll 8
        for (int k = 0; k < HID; k++)
            acc += s_h[r*HID + k] * w2[k*HID + t];
        X0[(b*NN + r)*HID + t] = fmaxf(acc, 0.f);
    }
}

// -------- GEMM: Y(BS*32, 512) = X(BS*32, DIN) @ W(DIN, 512) --------
// grid (BS, 2), 128 threads; each thread computes 2 cols x 32 rows
template<int DIN>
__global__ void gemm_k(const float* __restrict__ X, const float* __restrict__ W,
                       float* __restrict__ Y)
{
    __shared__ float Xs[NN*128];
    int b  = blockIdx.x;
    int c0 = blockIdx.y*256 + threadIdx.x;   // cols c0 and c0+128

    float acc0[NN], acc1[NN];
    #pragma unroll
    for (int r = 0; r < NN; r++) { acc0[r] = 0.f; acc1[r] = 0.f; }

    for (int kb = 0; kb < DIN; kb += 128) {
        __syncthreads();
        for (int i = threadIdx.x; i < NN*128; i += 128) {
            int r = i >> 7, c = i & 127;
            Xs[i] = X[(b*NN + r)*DIN + kb + c];
        }
        __syncthreads();
        #pragma unroll 4
        for (int k = 0; k < 128; k++) {
            float w0 = W[(kb + k)*D1 + c0];
            float w1 = W[(kb + k)*D1 + c0 + 128];
            #pragma unroll
            for (int r = 0; r < NN; r++) {
                float xv = Xs[r*128 + k];
                acc0[r] += xv * w0;
                acc1[r] += xv * w1;
            }
        }
    }
    #pragma unroll
    for (int r = 0; r < NN; r++) {
        Y[(b*NN + r)*D1 + c0]       = acc0[r];
        Y[(b*NN + r)*D1 + c0 + 128] = acc1[r];
    }
}

// -------- GATv2 attention per (batch, head): logits + softmax + aggregate --------
__global__ void attn_k(const float* __restrict__ GL, const float* __restrict__ GR,
                       const unsigned* __restrict__ ADJ,
                       const float* __restrict__ att, const float* __restrict__ bias,
                       float* __restrict__ Xout)
{
    __shared__ float gls[NN*129];
    __shared__ float grs[NN*129];
    __shared__ float lg[NN*NN];
    __shared__ float attv[HID];

    int b = blockIdx.x, h = blockIdx.y, t = threadIdx.x; // 128 threads

    attv[t] = att[h*HID + t];
    for (int i = t; i < NN*HID; i += 128) {
        int r = i >> 7, c = i & 127;
        gls[r*129 + c] = GL[(b*NN + r)*D1 + h*HID + c];
        grs[r*129 + c] = GR[(b*NN + r)*D1 + h*HID + c];
    }
    __syncthreads();

    // logits[i][j] = sum_c att[c] * leaky(gr[i,c] + gl[j,c]) if adj else -inf
    for (int idx = t; idx < NN*NN; idx += 128) {
        int i = idx >> 5, j = idx & 31;
        unsigned m = ADJ[b*NN + i];
        float s;
        if ((m >> j) & 1u) {
            s = 0.f;
            #pragma unroll 8
            for (int c = 0; c < HID; c++) {
                float v = grs[i*129 + c] + gls[j*129 + c];
                v = v > 0.f ? v : 0.2f * v;
                s += attv[c] * v;
            }
        } else {
            s = -1e30f;
        }
        lg[idx] = s;
    }
    __syncthreads();

    // softmax over j (threads 0..31, one row each)
    if (t < NN) {
        float mx = -1e30f;
        #pragma unroll
        for (int j = 0; j < NN; j++) mx = fmaxf(mx, lg[t*NN + j]);
        float e[NN], sum = 0.f;
        #pragma unroll
        for (int j = 0; j < NN; j++) { e[j] = expf(lg[t*NN + j] - mx); sum += e[j]; }
        float inv = 1.f / sum;
        #pragma unroll
        for (int j = 0; j < NN; j++) lg[t*NN + j] = e[j] * inv;
    }
    __syncthreads();

    // out[i][c] = relu(sum_j alpha[i][j] * gl[j][c] + bias); thread t = channel
    float bv = bias[h*HID + t];
    for (int i = 0; i < NN; i++) {
        float acc = 0.f;
        #pragma unroll
        for (int j = 0; j < NN; j++)
            acc += lg[i*NN + j] * gls[j*129 + t];
        Xout[(b*NN + i)*D1 + h*HID + t] = fmaxf(acc + bv, 0.f);
    }
}

// -------- dueling head: gather latent + 2-layer MLPs + advantage combine --------
__global__ void head_k(const float* __restrict__ obs,
                       const float* __restrict__ X0, const float* __restrict__ X1,
                       const float* __restrict__ X2,
                       const float* __restrict__ qw1, const float* __restrict__ qb1,
                       const float* __restrict__ qw2, const float* __restrict__ qb2,
                       const float* __restrict__ vw1, const float* __restrict__ vb1,
                       const float* __restrict__ vw2, const float* __restrict__ vb2,
                       float* __restrict__ out)
{
    __shared__ float xc[LATENT];
    __shared__ float qh[DUEL_H], vh[DUEL_H];
    __shared__ float qv[OUTD];
    __shared__ float vscal;

    int b = blockIdx.x, t = threadIdx.x; // 256 threads
    float av = obs[b*OBS_W + (OBS_W - 1)];
    av = fminf(fmaxf(av, 0.f), 31.f);
    int a = (int)av;

    if (t < HID) xc[t] = X0[(b*NN + a)*HID + t];
    for (int i = t; i < D1; i += 256) {
        xc[HID + i]      = X1[(b*NN + a)*D1 + i];
        xc[HID + D1 + i] = X2[(b*NN + a)*D1 + i];
    }
    __syncthreads();

    float aq = qb1[t], avv = vb1[t];
    #pragma unroll 8
    for (int k = 0; k < LATENT; k++) {
        float xv = xc[k];
        aq  += xv * qw1[k*DUEL_H + t];
        avv += xv * vw1[k*DUEL_H + t];
    }
    qh[t] = fmaxf(aq, 0.f);
    vh[t] = fmaxf(avv, 0.f);
    __syncthreads();

    if (t < OUTD) {
        float s = qb2[t];
        for (int k = 0; k < DUEL_H; k++) s += qh[k] * qw2[k*OUTD + t];
        qv[t] = s;
    }
    if (t == 8) {
        float s = vb2[0];
        for (int k = 0; k < DUEL_H; k++) s += vh[k] * vw2[k];
        vscal = s;
    }
    __syncthreads();

    if (t < OUTD) {
        float m = (qv[0] + qv[1] + qv[2] + qv[3] + qv[4]) * 0.2f;
        out[b*OUTD + t] = qv[t] - m + vscal;
    }
}

extern "C" void kernel_launch(void* const* d_in, const int* in_sizes, int n_in,
                              void* d_out, int out_size)
{
    const float* obs    = (const float*)d_in[0];
    const float* enc_w1 = (const float*)d_in[1];
    const float* enc_b1 = (const float*)d_in[2];
    const float* enc_w2 = (const float*)d_in[3];
    const float* enc_b2 = (const float*)d_in[4];
    const float* wl1    = (const float*)d_in[5];
    const float* wr1    = (const float*)d_in[6];
    const float* att1   = (const float*)d_in[7];
    const float* bias1  = (const float*)d_in[8];
    const float* wl2    = (const float*)d_in[9];
    const float* wr2    = (const float*)d_in[10];
    const float* att2   = (const float*)d_in[11];
    const float* bias2  = (const float*)d_in[12];
    const float* q_w1   = (const float*)d_in[13];
    const float* q_b1   = (const float*)d_in[14];
    const float* q_w2   = (const float*)d_in[15];
    const float* q_b2   = (const float*)d_in[16];
    const float* v_w1   = (const float*)d_in[17];
    const float* v_b1   = (const float*)d_in[18];
    const float* v_w2   = (const float*)d_in[19];
    const float* v_b2   = (const float*)d_in[20];
    float* out = (float*)d_out;

    float* X0;  cudaGetSymbolAddress((void**)&X0,  g_X0);
    unsigned* ADJ; cudaGetSymbolAddress((void**)&ADJ, g_ADJ);
    float* GL1; cudaGetSymbolAddress((void**)&GL1, g_GL1);
    float* GR1; cudaGetSymbolAddress((void**)&GR1, g_GR1);
    float* X1;  cudaGetSymbolAddress((void**)&X1,  g_X1);
    float* GL2; cudaGetSymbolAddress((void**)&GL2, g_GL2);
    float* GR2; cudaGetSymbolAddress((void**)&GR2, g_GR2);
    float* X2;  cudaGetSymbolAddress((void**)&X2,  g_X2);

    enc_kernel<<<BS, 128>>>(obs, enc_w1, enc_b1, enc_w2, enc_b2, X0, ADJ);

    gemm_k<HID><<<dim3(BS, 2), 128>>>(X0, wl1, GL1);
    gemm_k<HID><<<dim3(BS, 2), 128>>>(X0, wr1, GR1);
    attn_k<<<dim3(BS, HEADS), 128>>>(GL1, GR1, ADJ, att1, bias1, X1);

    gemm_k<D1><<<dim3(BS, 2), 128>>>(X1, wl2, GL2);
    gemm_k<D1><<<dim3(BS, 2), 128>>>(X1, wr2, GR2);
    attn_k<<<dim3(BS, HEADS), 128>>>(GL2, GR2, ADJ, att2, bias2, X2);

    head_k<<<BS, 256>>>(obs, X0, X1, X2,
                        q_w1, q_b1, q_w2, q_b2,
                        v_w1, v_b1, v_w2, v_b2, out);
}